// round 1
// baseline (speedup 1.0000x reference)
#include <cuda_runtime.h>
#include <math_constants.h>

#define HH 512
#define WW 512
#define BB 16
// window p=35, pad=17, chunk=35

// Intermediate: vertically eroded field, [B, H, W] fp32
__device__ float g_t[BB * HH * WW];
// Per-block partial sums from kernel 2 (32 row-groups x 16 batches = 512)
__device__ float g_partial[512];

// ---------------------------------------------------------------------------
// Kernel 1: channel-min of x fused with vertical (H-direction) min-filter,
// van Herk with chunk length 35. Block = (32 w, 8 chunks). Each chunk-thread
// produces 35 output rows for its 32-wide column strip.
// grid = (W/32, B, 2)  (2 groups of 8 chunks cover chunks 0..15; 0..14 valid)
// ---------------------------------------------------------------------------
__global__ __launch_bounds__(256) void k1_vert(const float* __restrict__ x) {
    __shared__ float sm[314 * 32];

    const int wx = threadIdx.x;
    const int ty = threadIdx.y;
    const int gw = blockIdx.x * 32 + wx;
    const int b  = blockIdx.y;
    const int h0 = blockIdx.z * 280;          // 8 chunks * 35 rows
    const float INF = CUDART_INF_F;

    // Load m = min over 3 channels of x into smem, rows [h0-17, h0+297)
    const float* xb = x + (size_t)b * 3 * HH * WW;
    for (int r = ty; r < 314; r += 8) {
        int gh = h0 - 17 + r;
        float m = INF;
        if ((unsigned)gh < HH) {
            size_t o = (size_t)gh * WW + gw;
            float a0 = xb[o];
            float a1 = xb[o + (size_t)HH * WW];
            float a2 = xb[o + (size_t)2 * HH * WW];
            m = fminf(a0, fminf(a1, a2));
        }
        sm[r * 32 + wx] = m;
    }
    __syncthreads();

    const int c    = blockIdx.z * 8 + ty;     // chunk index
    const int base = 35 * c;                  // first output row of chunk
    const int lb   = 35 * ty + 17;            // smem row of 'base'

    // Pass 1: suffix minima. q = base+34-k, local lq = lb+34-k.
    // Chunk boundary between q=base and q=base-1 -> reset at k==35.
    // Store S[q-base+17] = S[51-k] for q in [base-17, base+17] (k>=17).
    float S[35];
    float run = INF;
    #pragma unroll
    for (int k = 0; k < 52; k++) {
        if (k == 35) run = INF;
        float v = sm[(lb + 34 - k) * 32 + wx];
        run = fminf(run, v);
        if (k >= 17) S[51 - k] = run;
    }

    // Pass 2: prefix minima, emit out[i] = min(S_at(i-17), P_at(i+17)).
    run = INF;
    float* tb = g_t + (size_t)b * HH * WW;
    #pragma unroll
    for (int k = 0; k < 52; k++) {
        if (k == 35) run = INF;
        float v = sm[(lb + k) * 32 + wx];
        run = fminf(run, v);
        if (k >= 17) {
            int i = base + k - 17;
            if (i < HH) tb[(size_t)i * WW + gw] = fminf(S[k - 17], run);
        }
    }
}

// ---------------------------------------------------------------------------
// Kernel 2: horizontal (W-direction) min-filter + sum of erosion values.
// Block: 256 threads = 16 rows x 16 chunk-slots (chunk 15 idle, base=525).
// grid = (H/16, B); writes one partial sum per block (deterministic).
// ---------------------------------------------------------------------------
__global__ __launch_bounds__(256) void k2_horiz() {
    __shared__ float sm[16 * 512];
    __shared__ float red[256];

    const int tid = threadIdx.x;
    const int r0  = blockIdx.x * 16;
    const int b   = blockIdx.y;
    const float INF = CUDART_INF_F;

    const float* tb = g_t + (size_t)b * HH * WW + (size_t)r0 * WW;
    for (int i = tid; i < 16 * 512; i += 256) sm[i] = tb[i];
    __syncthreads();

    const int cx = tid & 15;   // chunk slot
    const int ry = tid >> 4;   // row within tile
    float acc = 0.0f;
    const int base = 35 * cx;

    if (base < WW) {
        float S[35];
        float run = INF;
        #pragma unroll
        for (int k = 0; k < 52; k++) {
            if (k == 35) run = INF;
            int q = base + 34 - k;
            float v = ((unsigned)q < WW) ? sm[ry * 512 + q] : INF;
            run = fminf(run, v);
            if (k >= 17) S[51 - k] = run;
        }
        run = INF;
        #pragma unroll
        for (int k = 0; k < 52; k++) {
            if (k == 35) run = INF;
            int q = base + k;
            float v = (q < WW) ? sm[ry * 512 + q] : INF;
            run = fminf(run, v);
            if (k >= 17) {
                int i = base + k - 17;
                if (i < WW) acc += fminf(S[k - 17], run);  // erosion e in [0,1]
            }
        }
    }

    red[tid] = acc;
    __syncthreads();
    #pragma unroll
    for (int s = 128; s > 0; s >>= 1) {
        if (tid < s) red[tid] += red[tid + s];
        __syncthreads();
    }
    if (tid == 0) g_partial[blockIdx.y * 32 + blockIdx.x] = red[0];
}

// ---------------------------------------------------------------------------
// Kernel 3: final reduction of 512 partials; loss = mean(erosion) - 1.
// ---------------------------------------------------------------------------
__global__ void k3_final(float* __restrict__ out) {
    __shared__ float red[512];
    int tid = threadIdx.x;
    red[tid] = g_partial[tid];
    __syncthreads();
    #pragma unroll
    for (int s = 256; s > 0; s >>= 1) {
        if (tid < s) red[tid] += red[tid + s];
        __syncthreads();
    }
    if (tid == 0) out[0] = red[0] * (1.0f / 4194304.0f) - 1.0f;
}

extern "C" void kernel_launch(void* const* d_in, const int* in_sizes, int n_in,
                              void* d_out, int out_size) {
    const float* x = (const float*)d_in[0];
    float* out = (float*)d_out;

    k1_vert<<<dim3(WW / 32, BB, 2), dim3(32, 8)>>>(x);
    k2_horiz<<<dim3(HH / 16, BB), 256>>>();
    k3_final<<<1, 512>>>(out);
}

// round 3
// speedup vs baseline: 1.0720x; 1.0720x over previous
#include <cuda_runtime.h>
#include <cuda_fp16.h>
#include <math_constants.h>

#define HH 512
#define WW 512
#define BB 16
// window p=35, pad=17, chunk=35
// loss = mean(erosion_35x35(min_c x)) - 1   (erosion = separable min filter)

// Intermediate: vertically eroded field, [B, H, W] as half (packed half2 pairs along W)
__device__ __align__(16) __half2 g_t2[BB * HH * WW / 2];
// Per-block partial sums from kernel 2 (32 row-groups x 16 batches = 512)
__device__ float g_partial[512];
// Completion counter for fused final reduction (reset each run)
__device__ int g_count;

// ---------------------------------------------------------------------------
// Kernel 1: channel-min of x (fp32 -> fp16) fused with vertical min-filter,
// van Herk chunk 35, half2 packed along W (2 columns/lane).
// Block = (32 lanes, 4 chunks) = 128 thr; tile = 64 W cols x 174 rows (22KB smem).
// grid = (W/64, B, 4)  (chunk c = z*4 + ty, c<15 valid)
// ---------------------------------------------------------------------------
__global__ __launch_bounds__(128) void k1_vert(const float* __restrict__ x) {
    __shared__ __half2 sm[174 * 32];

    const int tx  = threadIdx.x;
    const int ty  = threadIdx.y;
    const int tid = ty * 32 + tx;
    const int wc0 = blockIdx.x * 64;
    const int b   = blockIdx.y;
    const int z   = blockIdx.z;
    const int r0  = z * 140;                 // 4 chunks * 35 rows per z-group
    const float INF = CUDART_INF_F;

    // Load channel-min into smem rows [r0-17, r0+157), as half2 (2 W cols)
    const float* xb = x + (size_t)b * 3 * HH * WW;
    for (int j = tid; j < 174 * 16; j += 128) {
        int r  = j >> 4;
        int c4 = j & 15;                      // float4 slot within 64 cols
        int gh = r0 - 17 + r;
        float4 m;
        if ((unsigned)gh < HH) {
            const float4* p = (const float4*)(xb + (size_t)gh * WW + wc0 + c4 * 4);
            float4 a0 = p[0];
            float4 a1 = p[(HH * WW) / 4];
            float4 a2 = p[(2 * HH * WW) / 4];
            m.x = fminf(a0.x, fminf(a1.x, a2.x));
            m.y = fminf(a0.y, fminf(a1.y, a2.y));
            m.z = fminf(a0.z, fminf(a1.z, a2.z));
            m.w = fminf(a0.w, fminf(a1.w, a2.w));
        } else {
            m = make_float4(INF, INF, INF, INF);
        }
        sm[r * 32 + c4 * 2]     = __floats2half2_rn(m.x, m.y);
        sm[r * 32 + c4 * 2 + 1] = __floats2half2_rn(m.z, m.w);
    }
    __syncthreads();

    const int c    = z * 4 + ty;              // chunk index
    const int base = 35 * c;                  // first output row of chunk
    if (base >= HH) return;
    const int lb = 35 * ty + 17;              // smem row of 'base'
    const __half2 HINF = __float2half2_rn(CUDART_INF_F);

    // Pass 1: suffix minima (rows base+34 down to base-17, reset at chunk edge)
    __half2 S[35];
    __half2 run = HINF;
    #pragma unroll
    for (int k = 0; k < 52; k++) {
        if (k == 35) run = HINF;
        run = __hmin2(run, sm[(lb + 34 - k) * 32 + tx]);
        if (k >= 17) S[51 - k] = run;
    }

    // Pass 2: prefix minima, emit out[i] = min(S(i-17), P(i+17))
    run = HINF;
    const size_t ob = (size_t)b * HH;         // row base in g_t2
    const int wcol = (wc0 >> 1) + tx;         // half2 column
    #pragma unroll
    for (int k = 0; k < 52; k++) {
        if (k == 35) run = HINF;
        run = __hmin2(run, sm[(lb + k) * 32 + tx]);
        if (k >= 17) {
            int i = base + k - 17;
            if (i < HH)
                g_t2[(ob + i) * (WW / 2) + wcol] = __hmin2(S[k - 17], run);
        }
    }
}

// ---------------------------------------------------------------------------
// Kernel 2: horizontal min-filter (scalar half van Herk) + sum of erosion,
// fused deterministic final reduction in the last block.
// Block: 256 = 16 rows x 16 chunk-slots. grid = (H/16, B).
// ---------------------------------------------------------------------------
__global__ __launch_bounds__(256) void k2_horiz(float* __restrict__ out) {
    __shared__ __half smh[16 * 512];
    __shared__ float red[256];
    __shared__ int isLast;

    const int tid = threadIdx.x;
    const int r0  = blockIdx.x * 16;
    const int b   = blockIdx.y;

    // Load 16 rows x 512 halves (16KB) via uint4
    {
        const uint4* tb = (const uint4*)(g_t2 + ((size_t)b * HH + r0) * (WW / 2));
        uint4* smv = (uint4*)smh;
        #pragma unroll
        for (int i = 0; i < 4; i++) smv[tid + i * 256] = tb[tid + i * 256];
    }
    __syncthreads();

    const int cx = tid & 15;   // chunk slot
    const int ry = tid >> 4;   // row within tile
    float acc = 0.0f;
    const int base = 35 * cx;
    const __half HINF = __ushort_as_half((unsigned short)0x7C00);

    if (base < WW) {
        const int rb = ry * 512;
        __half S[35];
        __half run = HINF;
        #pragma unroll
        for (int k = 0; k < 52; k++) {
            if (k == 35) run = HINF;
            int q = base + 34 - k;
            __half v = ((unsigned)q < WW) ? smh[rb + q] : HINF;
            run = __hmin(run, v);
            if (k >= 17) S[51 - k] = run;
        }
        run = HINF;
        #pragma unroll
        for (int k = 0; k < 52; k++) {
            if (k == 35) run = HINF;
            int q = base + k;
            __half v = (q < WW) ? smh[rb + q] : HINF;
            run = __hmin(run, v);
            if (k >= 17) {
                int i = base + k - 17;
                if (i < WW) acc += __half2float(__hmin(S[k - 17], run));
            }
        }
    }

    // Deterministic in-block reduction
    red[tid] = acc;
    __syncthreads();
    #pragma unroll
    for (int s = 128; s > 0; s >>= 1) {
        if (tid < s) red[tid] += red[tid + s];
        __syncthreads();
    }
    if (tid == 0) {
        g_partial[blockIdx.y * 32 + blockIdx.x] = red[0];
        __threadfence();
        int done = atomicAdd(&g_count, 1);
        isLast = (done == 511) ? 1 : 0;
    }
    __syncthreads();

    // Last block: deterministic final reduction over the 512 partials
    if (isLast) {
        float v = g_partial[tid] + g_partial[tid + 256];
        red[tid] = v;
        __syncthreads();
        #pragma unroll
        for (int s = 128; s > 0; s >>= 1) {
            if (tid < s) red[tid] += red[tid + s];
            __syncthreads();
        }
        if (tid == 0) {
            out[0] = red[0] * (1.0f / 4194304.0f) - 1.0f;
            g_count = 0;   // reset for next graph replay
        }
    }
}

extern "C" void kernel_launch(void* const* d_in, const int* in_sizes, int n_in,
                              void* d_out, int out_size) {
    const float* x = (const float*)d_in[0];
    float* out = (float*)d_out;

    k1_vert<<<dim3(WW / 64, BB, 4), dim3(32, 4)>>>(x);
    k2_horiz<<<dim3(HH / 16, BB), 256>>>(out);
}

// round 4
// speedup vs baseline: 1.2284x; 1.1459x over previous
#include <cuda_runtime.h>
#include <cuda_fp16.h>
#include <math_constants.h>

#define HH 512
#define WW 512
#define BB 16
// window p=35, pad=17, chunk=35
// loss = mean(erosion_35x35(min_c x)) - 1   (erosion = separable min filter)

// Intermediate: vertically eroded field, [B, H, W] as half (packed half2 pairs along W)
__device__ __align__(16) __half2 g_t2[BB * HH * WW / 2];
// Per-block partial sums from kernel 2 (512 blocks)
__device__ float g_partial[512];
// Completion counter for fused final reduction (reset each run)
__device__ int g_count;

// ---------------------------------------------------------------------------
// Kernel 1: channel-min of x (fp32 -> fp16) fused with vertical min-filter,
// van Herk chunk 35, half2 packed along W (2 columns/lane).
// Block = (32 lanes, 4 chunks) = 128 thr; tile = 64 W cols x 174 rows (22KB smem).
// grid = (W/64, B, 4)  (chunk c = z*4 + ty, c<15 valid)
// ---------------------------------------------------------------------------
__global__ __launch_bounds__(128) void k1_vert(const float* __restrict__ x) {
    __shared__ __half2 sm[174 * 32];

    const int tx  = threadIdx.x;
    const int ty  = threadIdx.y;
    const int tid = ty * 32 + tx;
    const int wc0 = blockIdx.x * 64;
    const int b   = blockIdx.y;
    const int z   = blockIdx.z;
    const int r0  = z * 140;                 // 4 chunks * 35 rows per z-group
    const float INF = CUDART_INF_F;

    // Load channel-min into smem rows [r0-17, r0+157), as half2 (2 W cols)
    const float* xb = x + (size_t)b * 3 * HH * WW;
    for (int j = tid; j < 174 * 16; j += 128) {
        int r  = j >> 4;
        int c4 = j & 15;                      // float4 slot within 64 cols
        int gh = r0 - 17 + r;
        float4 m;
        if ((unsigned)gh < HH) {
            const float4* p = (const float4*)(xb + (size_t)gh * WW + wc0 + c4 * 4);
            float4 a0 = p[0];
            float4 a1 = p[(HH * WW) / 4];
            float4 a2 = p[(2 * HH * WW) / 4];
            m.x = fminf(a0.x, fminf(a1.x, a2.x));
            m.y = fminf(a0.y, fminf(a1.y, a2.y));
            m.z = fminf(a0.z, fminf(a1.z, a2.z));
            m.w = fminf(a0.w, fminf(a1.w, a2.w));
        } else {
            m = make_float4(INF, INF, INF, INF);
        }
        sm[r * 32 + c4 * 2]     = __floats2half2_rn(m.x, m.y);
        sm[r * 32 + c4 * 2 + 1] = __floats2half2_rn(m.z, m.w);
    }
    __syncthreads();

    const int c    = z * 4 + ty;              // chunk index
    const int base = 35 * c;                  // first output row of chunk
    if (base >= HH) return;
    const int lb = 35 * ty + 17;              // smem row of 'base'
    const __half2 HINF = __float2half2_rn(CUDART_INF_F);

    // Pass 1: suffix minima (rows base+34 down to base-17, reset at chunk edge)
    __half2 S[35];
    __half2 run = HINF;
    #pragma unroll
    for (int k = 0; k < 52; k++) {
        if (k == 35) run = HINF;
        run = __hmin2(run, sm[(lb + 34 - k) * 32 + tx]);
        if (k >= 17) S[51 - k] = run;
    }

    // Pass 2: prefix minima, emit out[i] = min(S(i-17), P(i+17))
    run = HINF;
    const size_t ob = (size_t)b * HH;         // row base in g_t2
    const int wcol = (wc0 >> 1) + tx;         // half2 column
    #pragma unroll
    for (int k = 0; k < 52; k++) {
        if (k == 35) run = HINF;
        run = __hmin2(run, sm[(lb + k) * 32 + tx]);
        if (k >= 17) {
            int i = base + k - 17;
            if (i < HH)
                g_t2[(ob + i) * (WW / 2) + wcol] = __hmin2(S[k - 17], run);
        }
    }
}

// ---------------------------------------------------------------------------
// Kernel 2: horizontal min-filter, restructured like k1's compute:
// half2 packs TWO IMAGE ROWS; smem tile is transposed [w-slot][row-pair]
// (pitch 33 half2 = 132B: conflict-free compute LDS).
// Block = (32 row-pair lanes, 4 w-chunks) = 128 thr; covers 64 rows x 140 cols.
// grid = (H/64, B, 4). Deterministic partial + fused last-block reduction.
// ---------------------------------------------------------------------------
__global__ __launch_bounds__(128) void k2_horiz(float* __restrict__ out) {
    __shared__ __half2 smh2[176 * 33];        // [tile w-slot][row-pair], 23.2KB
    __shared__ float red[128];
    __shared__ int isLast;

    const int tx  = threadIdx.x;              // row-pair lane
    const int ty  = threadIdx.y;              // w-chunk within block
    const int tid = ty * 32 + tx;
    const int h0  = blockIdx.x * 64;
    const int b   = blockIdx.y;
    const int z   = blockIdx.z;
    const int w0  = z * 140;                  // first output col of this z-group
    const __half2 HINF2 = __float2half2_rn(CUDART_INF_F);

    // Load tile: w slots [w0-18, w0+158) x 64 rows, transposed into smem.
    // 32 row-pairs x 88 half2-col-pairs = 2816 iters / 128 thr = 22 each.
    {
        const int pbase = 70 * z - 9;         // first half2-pair column index
        #pragma unroll
        for (int i = 0; i < 22; i++) {
            int j  = tid + i * 128;
            int rp = j / 88;                  // row-pair
            int tp = j - rp * 88;             // tile half2-pair slot
            int pc = pbase + tp;              // global half2 column
            __half2 a = HINF2, c = HINF2;
            if ((unsigned)pc < (WW / 2)) {
                size_t o = ((size_t)(b * HH + h0 + 2 * rp)) * (WW / 2) + pc;
                a = g_t2[o];                  // row 2rp   : (w, w+1)
                c = g_t2[o + WW / 2];         // row 2rp+1 : (w, w+1)
            }
            // repack to (row even, row odd) per w column
            smh2[(2 * tp) * 33 + rp]     = __lows2half2(a, c);
            smh2[(2 * tp + 1) * 33 + rp] = __highs2half2(a, c);
        }
    }
    __syncthreads();

    float acc = 0.0f;
    const int chunk = z * 4 + ty;
    const int basew = 35 * chunk;             // first output col of chunk
    if (basew < WW) {
        const int lb = 35 * ty + 18;          // tile slot of 'basew' (origin w0-18)

        // Pass 1: suffix minima
        __half2 S[35];
        __half2 run = HINF2;
        #pragma unroll
        for (int k = 0; k < 52; k++) {
            if (k == 35) run = HINF2;
            run = __hmin2(run, smh2[(lb + 34 - k) * 33 + tx]);
            if (k >= 17) S[51 - k] = run;
        }

        // Pass 2: prefix minima + combine + accumulate (erosion values in [0,1])
        run = HINF2;
        #pragma unroll
        for (int k = 0; k < 52; k++) {
            if (k == 35) run = HINF2;
            run = __hmin2(run, smh2[(lb + k) * 33 + tx]);
            if (k >= 17) {
                int iw = basew + k - 17;
                if (iw < WW) {
                    float2 e = __half22float2(__hmin2(S[k - 17], run));
                    acc += e.x + e.y;
                }
            }
        }
    }

    // Deterministic in-block reduction (128 threads)
    red[tid] = acc;
    __syncthreads();
    #pragma unroll
    for (int s = 64; s > 0; s >>= 1) {
        if (tid < s) red[tid] += red[tid + s];
        __syncthreads();
    }
    if (tid == 0) {
        g_partial[b * 32 + z * 8 + blockIdx.x] = red[0];
        __threadfence();
        int done = atomicAdd(&g_count, 1);
        isLast = (done == 511) ? 1 : 0;
    }
    __syncthreads();

    // Last block: deterministic final reduction over the 512 partials
    if (isLast) {
        float v = g_partial[tid] + g_partial[tid + 128] +
                  g_partial[tid + 256] + g_partial[tid + 384];
        red[tid] = v;
        __syncthreads();
        #pragma unroll
        for (int s = 64; s > 0; s >>= 1) {
            if (tid < s) red[tid] += red[tid + s];
            __syncthreads();
        }
        if (tid == 0) {
            out[0] = red[0] * (1.0f / 4194304.0f) - 1.0f;
            g_count = 0;   // reset for next graph replay
        }
    }
}

extern "C" void kernel_launch(void* const* d_in, const int* in_sizes, int n_in,
                              void* d_out, int out_size) {
    const float* x = (const float*)d_in[0];
    float* out = (float*)d_out;

    k1_vert<<<dim3(WW / 64, BB, 4), dim3(32, 4)>>>(x);
    k2_horiz<<<dim3(HH / 64, BB, 4), dim3(32, 4)>>>(out);
}